// round 14
// baseline (speedup 1.0000x reference)
#include <cuda_runtime.h>
#include <cuda_bf16.h>
#include <math.h>

#define NN 50000
#define NE 800000
#define HID 64
#define LAYERS 4
#define MLPH 128
#define AP 72            // bf16 smem row pitch (144B => LDSM conflict-free)

typedef unsigned long long ull;
typedef unsigned int u32;

// ---------------- device state ----------------
__device__ float g_h[NN * HID];
__device__ u32   g_e[NE * HID];            // packed (bf16 hi | bf16 lo<<16), CSR order
__device__ float g_nodeT[NN * 4 * HID];    // per node: [A|B|D|E]
__device__ float g_num[NN * HID];          // zero-init; zero-after-consume
__device__ float g_den[NN * HID];
__device__ float g_mlp[NN * MLPH];
__device__ __nv_bfloat16 g_WnT[LAYERS][2][256][64];
__device__ __nv_bfloat16 g_WcT[LAYERS][2][64][64];
__device__ __nv_bfloat16 g_W1T[2][128][64];
__device__ int   g_count[NN];
__device__ int   g_rowstart[NN + 1];
__device__ int   g_cursor[NN];
__device__ int   g_perm_src[NE];
__device__ int   g_perm_dst[NE];
__device__ int   g_perm_eid[NE];

// ---------------- helpers ----------------
__device__ __forceinline__ float fsig(float t) {
    return __fdividef(1.f, 1.f + __expf(-t));
}
__device__ __forceinline__ u32 packsplit(float x) {
    __nv_bfloat16 h = __float2bfloat16(x);
    float r = x - __bfloat162float(h);
    __nv_bfloat16 l = __float2bfloat16(r);
    return (u32)__bfloat16_as_ushort(h) | ((u32)__bfloat16_as_ushort(l) << 16);
}
__device__ __forceinline__ float frombits(u32 h16, u32 l16) {
    return __bfloat162float(__ushort_as_bfloat16((unsigned short)h16)) +
           __bfloat162float(__ushort_as_bfloat16((unsigned short)l16));
}
__device__ __forceinline__ void mma16816(float c[4], u32 a0, u32 a1, u32 a2, u32 a3,
                                         u32 b0, u32 b1) {
    asm volatile(
        "mma.sync.aligned.m16n8k16.row.col.f32.bf16.bf16.f32 "
        "{%0,%1,%2,%3},{%4,%5,%6,%7},{%8,%9},{%0,%1,%2,%3};"
        : "+f"(c[0]), "+f"(c[1]), "+f"(c[2]), "+f"(c[3])
        : "r"(a0), "r"(a1), "r"(a2), "r"(a3), "r"(b0), "r"(b1));
}
__device__ __forceinline__ void ldsm4(u32& r0, u32& r1, u32& r2, u32& r3, u32 addr) {
    asm volatile("ldmatrix.sync.aligned.m8n8.x4.shared.b16 {%0,%1,%2,%3}, [%4];"
                 : "=r"(r0), "=r"(r1), "=r"(r2), "=r"(r3) : "r"(addr));
}
__device__ __forceinline__ u32 s2u(const void* p) {
    return (u32)__cvta_generic_to_shared(p);
}

// ---------------- CSR hist + fused weight prep ----------------
__global__ void k_hist(const int* __restrict__ dst, const float* __restrict__ WL,
                       const float* __restrict__ W1) {
    int b = blockIdx.x;
    int e = b * 256 + threadIdx.x;
    if (e < NE) atomicAdd(&g_count[dst[e]], 1);
    if (b < LAYERS) {
        const float* Wn = WL + (size_t)b * 5 * 4096;
        for (int q = threadIdx.x; q < 4 * 4096; q += 256) {
            int j = q >> 12, k = (q >> 6) & 63, c = q & 63;
            float x = Wn[q];
            __nv_bfloat16 h = __float2bfloat16(x);
            g_WnT[b][0][j * 64 + c][k] = h;
            g_WnT[b][1][j * 64 + c][k] = __float2bfloat16(x - __bfloat162float(h));
        }
        const float* Wc = WL + (size_t)b * 5 * 4096 + 4 * 4096;
        for (int q = threadIdx.x; q < 4096; q += 256) {
            int k = q >> 6, c = q & 63;
            float x = Wc[q];
            __nv_bfloat16 h = __float2bfloat16(x);
            g_WcT[b][0][c][k] = h;
            g_WcT[b][1][c][k] = __float2bfloat16(x - __bfloat162float(h));
        }
    } else if (b == LAYERS) {
        for (int q = threadIdx.x; q < 8192; q += 256) {
            int k = q >> 7, c = q & 127;
            float x = W1[q];
            __nv_bfloat16 h = __float2bfloat16(x);
            g_W1T[0][c][k] = h;
            g_W1T[1][c][k] = __float2bfloat16(x - __bfloat162float(h));
        }
    }
}

__global__ void k_scan() {   // single block; self-zeroes g_count for replay
    __shared__ int part[1024];
    int tid = threadIdx.x;
    const int CH = (NN + 1023) / 1024;
    int base = tid * CH;
    int s = 0;
    for (int i = 0; i < CH; i++) { int idx = base + i; if (idx < NN) s += g_count[idx]; }
    part[tid] = s;
    __syncthreads();
    for (int off = 1; off < 1024; off <<= 1) {
        int v = (tid >= off) ? part[tid - off] : 0;
        __syncthreads();
        part[tid] += v;
        __syncthreads();
    }
    int excl = part[tid] - s;
    for (int i = 0; i < CH; i++) {
        int idx = base + i;
        if (idx < NN) {
            int c = g_count[idx];
            g_rowstart[idx] = excl;
            g_cursor[idx] = excl;
            excl += c;
            g_count[idx] = 0;
        }
    }
    if (tid == 1023) g_rowstart[NN] = part[1023];
}
__global__ void k_scatter(const int* __restrict__ src, const int* __restrict__ dst) {
    int e = blockIdx.x * blockDim.x + threadIdx.x;
    if (e < NE) {
        int d = dst[e];
        int pos = atomicAdd(&g_cursor[d], 1);
        g_perm_src[pos] = src[e];
        g_perm_dst[pos] = d;
        g_perm_eid[pos] = e;
    }
}

// ---------------- node MMA GEMM: C[M, nq*64] = A[M,64] @ W + bias ----------------
__global__ void __launch_bounds__(256, 5) k_node_mma(
    const __nv_bfloat16* __restrict__ WT,
    const float* __restrict__ bias, float* __restrict__ C,
    int M, int nq, int ldc, int relu,
    const float* __restrict__ hf, const float* __restrict__ Wemb,
    const float* __restrict__ bemb, int embedH, int updateH)
{
    __shared__ __align__(16) __nv_bfloat16 Apl[2][64 * AP];
    __shared__ __align__(16) __nv_bfloat16 Wq[2][64 * AP];
    int n0 = blockIdx.x * 64;
    int t = threadIdx.x;
    int lane = t & 31, w = t >> 5;
    int nTot = nq * 64;

#pragma unroll
    for (int i = 0; i < 4; i++) {
        int q = i * 256 + t;
        int row = q >> 4, c0 = (q & 15) * 4;
        int m = n0 + row;
        float4 v = make_float4(0.f, 0.f, 0.f, 0.f);
        if (m < M) {
            if (embedH) {
                float f[6];
#pragma unroll
                for (int j = 0; j < 6; j++) f[j] = hf[m * 6 + j];
                v = *(const float4*)(bemb + c0);
#pragma unroll
                for (int j = 0; j < 6; j++) {
                    float4 wv = *(const float4*)(Wemb + j * 64 + c0);
                    v.x = fmaf(f[j], wv.x, v.x);
                    v.y = fmaf(f[j], wv.y, v.y);
                    v.z = fmaf(f[j], wv.z, v.z);
                    v.w = fmaf(f[j], wv.w, v.w);
                }
                *(float4*)(g_h + (size_t)m * 64 + c0) = v;
            } else if (updateH) {
                float4 hv = *(const float4*)(g_h + (size_t)m * 64 + c0);
                float4 ah = *(const float4*)(g_nodeT + (size_t)m * 256 + c0);
                float4 nu = *(const float4*)(g_num + (size_t)m * 64 + c0);
                float4 de = *(const float4*)(g_den + (size_t)m * 64 + c0);
                *(float4*)(g_num + (size_t)m * 64 + c0) = make_float4(0.f, 0.f, 0.f, 0.f);
                *(float4*)(g_den + (size_t)m * 64 + c0) = make_float4(0.f, 0.f, 0.f, 0.f);
                v.x = hv.x + fmaxf(ah.x + nu.x * __fdividef(1.f, de.x + 1e-6f), 0.f);
                v.y = hv.y + fmaxf(ah.y + nu.y * __fdividef(1.f, de.y + 1e-6f), 0.f);
                v.z = hv.z + fmaxf(ah.z + nu.z * __fdividef(1.f, de.z + 1e-6f), 0.f);
                v.w = hv.w + fmaxf(ah.w + nu.w * __fdividef(1.f, de.w + 1e-6f), 0.f);
                *(float4*)(g_h + (size_t)m * 64 + c0) = v;
            } else {
                v = *(const float4*)(g_h + (size_t)m * 64 + c0);
            }
        }
        u32 p0 = packsplit(v.x), p1 = packsplit(v.y);
        u32 p2 = packsplit(v.z), p3 = packsplit(v.w);
        *(uint2*)&Apl[0][row * AP + c0] =
            make_uint2(__byte_perm(p0, p1, 0x5410), __byte_perm(p2, p3, 0x5410));
        *(uint2*)&Apl[1][row * AP + c0] =
            make_uint2(__byte_perm(p0, p1, 0x7632), __byte_perm(p2, p3, 0x7632));
    }

    int ms = w >> 1, nh = w & 1;
    int gid = lane >> 2, tig = lane & 3;

    u32 aOff = (u32)(((ms * 16 + (lane & 7) + ((lane >> 3) & 1) * 8) * AP +
                      (lane >> 4) * 8) * 2);
    u32 aHiB = s2u(&Apl[0][0]) + aOff;
    u32 aLoB = s2u(&Apl[1][0]) + aOff;
    u32 bB[4];
#pragma unroll
    for (int nt = 0; nt < 4; nt++) {
        int nrow = nh * 32 + nt * 8 + (lane & 7);
        bB[nt] = s2u(&Wq[0][0]) +
                 (u32)((nrow * AP + ((lane >> 3) & 1) * 8) * 2) +
                 (u32)((lane >> 4) * 64 * AP * 2);
    }

    for (int q = 0; q < nq; q++) {
        __syncthreads();
        {
            int n = t >> 2, ks = (t & 3) * 16;
            const __nv_bfloat16* Wh = WT + (size_t)(q * 64 + n) * 64;
            const __nv_bfloat16* Wl = WT + (size_t)nTot * 64 + (size_t)(q * 64 + n) * 64;
            *(uint4*)&Wq[0][n * AP + ks]     = *(const uint4*)(Wh + ks);
            *(uint4*)&Wq[0][n * AP + ks + 8] = *(const uint4*)(Wh + ks + 8);
            *(uint4*)&Wq[1][n * AP + ks]     = *(const uint4*)(Wl + ks);
            *(uint4*)&Wq[1][n * AP + ks + 8] = *(const uint4*)(Wl + ks + 8);
        }
        __syncthreads();

        float c[4][4];
#pragma unroll
        for (int nt = 0; nt < 4; nt++)
#pragma unroll
            for (int j = 0; j < 4; j++) c[nt][j] = 0.f;

#pragma unroll
        for (int kc = 0; kc < 4; kc++) {
            u32 ko = kc * 32;
            u32 a0h, a1h, a2h, a3h, a0l, a1l, a2l, a3l;
            ldsm4(a0h, a1h, a2h, a3h, aHiB + ko);
            ldsm4(a0l, a1l, a2l, a3l, aLoB + ko);
#pragma unroll
            for (int nt = 0; nt < 4; nt++) {
                u32 b0h, b1h, b0l, b1l;
                ldsm4(b0h, b1h, b0l, b1l, bB[nt] + ko);
                mma16816(c[nt], a0h, a1h, a2h, a3h, b0h, b1h);
                mma16816(c[nt], a0h, a1h, a2h, a3h, b0l, b1l);
                mma16816(c[nt], a0l, a1l, a2l, a3l, b0h, b1h);
            }
        }

#pragma unroll
        for (int nt = 0; nt < 4; nt++) {
            int col = q * 64 + nh * 32 + nt * 8 + tig * 2;
            int r = n0 + ms * 16 + gid;
            float b0 = bias[col], b1 = bias[col + 1];
            float2 v0 = make_float2(c[nt][0] + b0, c[nt][1] + b1);
            float2 v1 = make_float2(c[nt][2] + b0, c[nt][3] + b1);
            if (relu) {
                v0.x = fmaxf(v0.x, 0.f); v0.y = fmaxf(v0.y, 0.f);
                v1.x = fmaxf(v1.x, 0.f); v1.y = fmaxf(v1.y, 0.f);
            }
            if (r < M)     *(float2*)(C + (size_t)r * ldc + col)       = v0;
            if (r + 8 < M) *(float2*)(C + (size_t)(r + 8) * ldc + col) = v1;
        }
    }
}

// ---------------- fused edge MMA + gate + e-residual + direct atomic reduction ----------------
#define OFF_ALO   9216
#define OFF_WT    18432
#define OFF_WTLO  27648
#define OFF_SRC   36864
#define OFF_DST   37120
#define OFF_EF    37376
// Cs (float[64][68]=17408B) overlays W planes [18432, 36864): Ce stage

__global__ void __launch_bounds__(256, 5) k_edge_gemm(
    const __nv_bfloat16* __restrict__ WT, const float* __restrict__ bc,
    const float* __restrict__ We, const float* __restrict__ be,
    const float* __restrict__ ef, int embed, int last)
{
    __shared__ __align__(16) char sm[37888];
    __nv_bfloat16* Ahi = (__nv_bfloat16*)sm;
    __nv_bfloat16* Alo = (__nv_bfloat16*)(sm + OFF_ALO);
    __nv_bfloat16* Wth = (__nv_bfloat16*)(sm + OFF_WT);
    __nv_bfloat16* Wtl = (__nv_bfloat16*)(sm + OFF_WTLO);
    float* Cs = (float*)(sm + OFF_WT);   // Ce stage (over dead W planes)
    int*   sSrc = (int*)(sm + OFF_SRC);
    int*   sDst = (int*)(sm + OFF_DST);
    float2* sEf = (float2*)(sm + OFF_EF);

    int p0 = blockIdx.x * 64;
    int t = threadIdx.x;
    int lane = t & 31, w = t >> 5;
    int tx = t & 15, ty = t >> 4;

    if (t < 64) {
        sSrc[t] = g_perm_src[p0 + t];
        sDst[t] = g_perm_dst[p0 + t];
        if (embed) sEf[t] = ((const float2*)ef)[g_perm_eid[p0 + t]];
    }
    {
        int n = t >> 2, ks = (t & 3) * 16;
        *(uint4*)&Wth[n * AP + ks]     = *(const uint4*)(WT + n * 64 + ks);
        *(uint4*)&Wth[n * AP + ks + 8] = *(const uint4*)(WT + n * 64 + ks + 8);
        *(uint4*)&Wtl[n * AP + ks]     = *(const uint4*)(WT + 4096 + n * 64 + ks);
        *(uint4*)&Wtl[n * AP + ks + 8] = *(const uint4*)(WT + 4096 + n * 64 + ks + 8);
    }
    if (embed) __syncthreads();   // B0 (embed only): sEf published before A-build

#pragma unroll
    for (int i = 0; i < 4; i++) {
        int q = i * 256 + t;
        int row = q >> 4, c0 = (q & 15) * 4;
        uint4 u;
        if (embed) {
            float2 efv = sEf[row];
            float4 w0 = *(const float4*)(We + c0);
            float4 w1 = *(const float4*)(We + 64 + c0);
            float4 bb = *(const float4*)(be + c0);
            u.x = packsplit(fmaf(efv.x, w0.x, fmaf(efv.y, w1.x, bb.x)));
            u.y = packsplit(fmaf(efv.x, w0.y, fmaf(efv.y, w1.y, bb.y)));
            u.z = packsplit(fmaf(efv.x, w0.z, fmaf(efv.y, w1.z, bb.z)));
            u.w = packsplit(fmaf(efv.x, w0.w, fmaf(efv.y, w1.w, bb.w)));
        } else {
            u = __ldcs((const uint4*)&g_e[(size_t)(p0 + row) * 64 + c0]);  // streaming: keep nodeT in L2
        }
        *(uint2*)&Ahi[row * AP + c0] =
            make_uint2(__byte_perm(u.x, u.y, 0x5410), __byte_perm(u.z, u.w, 0x5410));
        *(uint2*)&Alo[row * AP + c0] =
            make_uint2(__byte_perm(u.x, u.y, 0x7632), __byte_perm(u.z, u.w, 0x7632));
    }
    __syncthreads();   // B1: A planes + W planes + aux ready

    int ms = w >> 1, nh = w & 1;
    int gid = lane >> 2, tig = lane & 3;

    u32 aOff = (u32)(((ms * 16 + (lane & 7) + ((lane >> 3) & 1) * 8) * AP +
                      (lane >> 4) * 8) * 2);
    u32 aHiB = s2u(Ahi) + aOff;
    u32 aLoB = s2u(Alo) + aOff;
    u32 bB[4];
#pragma unroll
    for (int nt = 0; nt < 4; nt++) {
        int nrow = nh * 32 + nt * 8 + (lane & 7);
        bB[nt] = s2u(Wth) +
                 (u32)((nrow * AP + ((lane >> 3) & 1) * 8) * 2) +
                 (u32)((lane >> 4) * (OFF_WTLO - OFF_WT));
    }

    float c[4][4];
#pragma unroll
    for (int nt = 0; nt < 4; nt++)
#pragma unroll
        for (int j = 0; j < 4; j++) c[nt][j] = 0.f;

#pragma unroll
    for (int kc = 0; kc < 4; kc++) {
        u32 ko = kc * 32;
        u32 a0h, a1h, a2h, a3h, a0l, a1l, a2l, a3l;
        ldsm4(a0h, a1h, a2h, a3h, aHiB + ko);
        ldsm4(a0l, a1l, a2l, a3l, aLoB + ko);
#pragma unroll
        for (int nt = 0; nt < 4; nt++) {
            u32 b0h, b1h, b0l, b1l;
            ldsm4(b0h, b1h, b0l, b1l, bB[nt] + ko);
            mma16816(c[nt], a0h, a1h, a2h, a3h, b0h, b1h);
            mma16816(c[nt], a0h, a1h, a2h, a3h, b0l, b1l);
            mma16816(c[nt], a0l, a1l, a2l, a3l, b0h, b1h);
        }
    }
    __syncthreads();   // B2: all ldsm done -> Cs overlay of W planes safe

    // stage Ce fragments
#pragma unroll
    for (int nt = 0; nt < 4; nt++) {
        int col = nh * 32 + nt * 8 + tig * 2;
        int r = ms * 16 + gid;
        *(float2*)&Cs[r * 68 + col]       = make_float2(c[nt][0], c[nt][1]);
        *(float2*)&Cs[(r + 8) * 68 + col] = make_float2(c[nt][2], c[nt][3]);
    }
    __syncthreads();   // B3: Ce staged

    float bb0 = bc[tx * 4 + 0], bb1 = bc[tx * 4 + 1];
    float bb2 = bc[tx * 4 + 2], bb3 = bc[tx * 4 + 3];

    // Gate + e-residual + run-aggregated direct atomic reduction.
    // Thread owns rows ty*4..ty*4+3 x cols tx*4..tx*4+3 (dst-sorted rows).
    {
        float an0 = 0.f, an1 = 0.f, an2 = 0.f, an3 = 0.f;
        float ad0 = 0.f, ad1 = 0.f, ad2 = 0.f, ad3 = 0.f;
        int curd = sDst[ty * 4];
#pragma unroll
        for (int r = 0; r < 4; r++) {
            int row = ty * 4 + r;
            int p = p0 + row;
            int dn = sDst[row], sn = sSrc[row];
            if (dn != curd) {   // flush finished run
                float* np = g_num + (size_t)curd * 64 + tx * 4;
                float* dp = g_den + (size_t)curd * 64 + tx * 4;
                atomicAdd(np + 0, an0); atomicAdd(np + 1, an1);
                atomicAdd(np + 2, an2); atomicAdd(np + 3, an3);
                atomicAdd(dp + 0, ad0); atomicAdd(dp + 1, ad1);
                atomicAdd(dp + 2, ad2); atomicAdd(dp + 3, ad3);
                an0 = an1 = an2 = an3 = 0.f;
                ad0 = ad1 = ad2 = ad3 = 0.f;
                curd = dn;
            }
            float4 dh = *(const float4*)(g_nodeT + (size_t)dn * 256 + 128 + tx * 4);
            float4 eh = *(const float4*)(g_nodeT + (size_t)sn * 256 + 192 + tx * 4);
            float4 bh = *(const float4*)(g_nodeT + (size_t)sn * 256 +  64 + tx * 4);
            float4 ce = *(const float4*)&Cs[row * 68 + tx * 4];
            uint2 hu = *(const uint2*)&Ahi[row * AP + tx * 4];
            uint2 lu = *(const uint2*)&Alo[row * AP + tx * 4];
            float eo0 = frombits(hu.x & 0xffffu, lu.x & 0xffffu);
            float eo1 = frombits(hu.x >> 16,     lu.x >> 16);
            float eo2 = frombits(hu.y & 0xffffu, lu.y & 0xffffu);
            float eo3 = frombits(hu.y >> 16,     lu.y >> 16);
            float t0 = ce.x + bb0 + dh.x + eh.x;
            float t1 = ce.y + bb1 + dh.y + eh.y;
            float t2 = ce.z + bb2 + dh.z + eh.z;
            float t3 = ce.w + bb3 + dh.w + eh.w;
            float s0 = fsig(t0), s1 = fsig(t1), s2 = fsig(t2), s3 = fsig(t3);
            if (!last) {
                uint4 en;
                en.x = packsplit(eo0 + fmaxf(t0, 0.f));
                en.y = packsplit(eo1 + fmaxf(t1, 0.f));
                en.z = packsplit(eo2 + fmaxf(t2, 0.f));
                en.w = packsplit(eo3 + fmaxf(t3, 0.f));
                __stcs((uint4*)&g_e[(size_t)p * 64 + tx * 4], en);   // streaming store
            }
            an0 = fmaf(s0, bh.x, an0); an1 = fmaf(s1, bh.y, an1);
            an2 = fmaf(s2, bh.z, an2); an3 = fmaf(s3, bh.w, an3);
            ad0 += s0; ad1 += s1; ad2 += s2; ad3 += s3;
        }
        // final flush
        float* np = g_num + (size_t)curd * 64 + tx * 4;
        float* dp = g_den + (size_t)curd * 64 + tx * 4;
        atomicAdd(np + 0, an0); atomicAdd(np + 1, an1);
        atomicAdd(np + 2, an2); atomicAdd(np + 3, an3);
        atomicAdd(dp + 0, ad0); atomicAdd(dp + 1, ad1);
        atomicAdd(dp + 2, ad2); atomicAdd(dp + 3, ad3);
    }
}

// ---------------- MLP head tail ----------------
__global__ void k_head(const float* __restrict__ W2, const float* __restrict__ b2,
                       float* __restrict__ out) {
    int gtid = blockIdx.x * blockDim.x + threadIdx.x;
    int n = gtid >> 5;
    if (n >= NN) return;
    int lane = gtid & 31;
    float s0 = 0.f, s1 = 0.f;
#pragma unroll
    for (int t = 0; t < 4; t++) {
        int k = lane + t * 32;
        float v = g_mlp[n * 128 + k];
        s0 = fmaf(v, W2[k * 2 + 0], s0);
        s1 = fmaf(v, W2[k * 2 + 1], s1);
    }
#pragma unroll
    for (int off = 16; off; off >>= 1) {
        s0 += __shfl_xor_sync(0xffffffffu, s0, off);
        s1 += __shfl_xor_sync(0xffffffffu, s1, off);
    }
    if (lane == 0) {
        out[n * 2 + 0] = -1.2f * tanhf(s0 + b2[0]);
        out[n * 2 + 1] = -1.2f * tanhf(s1 + b2[1]);
    }
}

// ---------------- launch ----------------
extern "C" void kernel_launch(void* const* d_in, const int* in_sizes, int n_in,
                              void* d_out, int out_size) {
    const float* h_feat  = (const float*)d_in[0];
    const float* e_feat  = (const float*)d_in[1];
    const int*   src     = (const int*)d_in[2];
    const int*   dst     = (const int*)d_in[3];
    const float* W_emb_h = (const float*)d_in[4];
    const float* b_emb_h = (const float*)d_in[5];
    const float* W_emb_e = (const float*)d_in[6];
    const float* b_emb_e = (const float*)d_in[7];
    const float* WL      = (const float*)d_in[8];
    const float* bL      = (const float*)d_in[9];
    const float* W1      = (const float*)d_in[10];
    const float* b1      = (const float*)d_in[11];
    const float* W2      = (const float*)d_in[12];
    const float* b2      = (const float*)d_in[13];
    float* out = (float*)d_out;

    void *p_nodeT, *p_mlp, *p_WnT, *p_WcT, *p_W1T;
    cudaGetSymbolAddress(&p_nodeT, g_nodeT);
    cudaGetSymbolAddress(&p_mlp, g_mlp);
    cudaGetSymbolAddress(&p_WnT, g_WnT);
    cudaGetSymbolAddress(&p_WcT, g_WcT);
    cudaGetSymbolAddress(&p_W1T, g_W1T);

    // CSR build (hist fuses weight split/transpose prep)
    k_hist<<<(NE + 255) / 256, 256>>>(dst, WL, W1);
    k_scan<<<1, 1024>>>();
    k_scatter<<<(NE + 255) / 256, 256>>>(src, dst);

    for (int l = 0; l < LAYERS; l++) {
        const float* bl = bL + (size_t)l * 5 * HID;
        const __nv_bfloat16* WnT =
            (const __nv_bfloat16*)p_WnT + (size_t)l * 2 * 256 * 64;
        const __nv_bfloat16* WcT =
            (const __nv_bfloat16*)p_WcT + (size_t)l * 2 * 64 * 64;
        k_node_mma<<<(NN + 63) / 64, 256>>>(
            WnT, bl, (float*)p_nodeT, NN, 4, 256, 0,
            h_feat, W_emb_h, b_emb_h, l == 0, l > 0);
        k_edge_gemm<<<NE / 64, 256>>>(WcT, bl + 4 * 64,
                                      W_emb_e, b_emb_e, e_feat,
                                      l == 0, l == LAYERS - 1);
    }

    k_node_mma<<<(NN + 63) / 64, 256>>>(
        (const __nv_bfloat16*)p_W1T, b1, (float*)p_mlp, NN, 2, 128, 1,
        (const float*)0, (const float*)0, (const float*)0, 0, 1);
    k_head<<<(NN * 32 + 255) / 256, 256>>>(W2, b2, out);
}

// round 16
// speedup vs baseline: 1.0803x; 1.0803x over previous
#include <cuda_runtime.h>
#include <cuda_bf16.h>
#include <math.h>

#define NN 50000
#define NE 800000
#define HID 64
#define LAYERS 4
#define MLPH 128
#define AP 72            // bf16 smem row pitch (144B => LDSM conflict-free)

typedef unsigned long long ull;
typedef unsigned int u32;

// ---------------- device state ----------------
__device__ float g_h[NN * HID];
__device__ u32   g_e[NE * HID];            // packed (bf16 hi | bf16 lo<<16), CSR order
__device__ float g_nodeT[NN * 4 * HID];    // per node: [A|B|D|E]
__device__ float g_num[NN * HID];          // zero-init; zero-after-consume
__device__ float g_den[NN * HID];
__device__ float g_mlp[NN * MLPH];
__device__ __nv_bfloat16 g_WnT[LAYERS][2][256][64];
__device__ __nv_bfloat16 g_WcT[LAYERS][2][64][64];
__device__ __nv_bfloat16 g_W1T[2][128][64];
__device__ int   g_count[NN];
__device__ int   g_rowstart[NN + 1];
__device__ int   g_cursor[NN];
__device__ int   g_perm_src[NE];
__device__ int   g_perm_dst[NE];
__device__ int   g_perm_eid[NE];

// ---------------- helpers ----------------
__device__ __forceinline__ float fsig(float t) {
    return __fdividef(1.f, 1.f + __expf(-t));
}
__device__ __forceinline__ u32 packsplit(float x) {
    __nv_bfloat16 h = __float2bfloat16(x);
    float r = x - __bfloat162float(h);
    __nv_bfloat16 l = __float2bfloat16(r);
    return (u32)__bfloat16_as_ushort(h) | ((u32)__bfloat16_as_ushort(l) << 16);
}
__device__ __forceinline__ float frombits(u32 h16, u32 l16) {
    return __bfloat162float(__ushort_as_bfloat16((unsigned short)h16)) +
           __bfloat162float(__ushort_as_bfloat16((unsigned short)l16));
}
__device__ __forceinline__ void mma16816(float c[4], u32 a0, u32 a1, u32 a2, u32 a3,
                                         u32 b0, u32 b1) {
    asm volatile(
        "mma.sync.aligned.m16n8k16.row.col.f32.bf16.bf16.f32 "
        "{%0,%1,%2,%3},{%4,%5,%6,%7},{%8,%9},{%0,%1,%2,%3};"
        : "+f"(c[0]), "+f"(c[1]), "+f"(c[2]), "+f"(c[3])
        : "r"(a0), "r"(a1), "r"(a2), "r"(a3), "r"(b0), "r"(b1));
}
__device__ __forceinline__ void ldsm4(u32& r0, u32& r1, u32& r2, u32& r3, u32 addr) {
    asm volatile("ldmatrix.sync.aligned.m8n8.x4.shared.b16 {%0,%1,%2,%3}, [%4];"
                 : "=r"(r0), "=r"(r1), "=r"(r2), "=r"(r3) : "r"(addr));
}
__device__ __forceinline__ u32 s2u(const void* p) {
    return (u32)__cvta_generic_to_shared(p);
}
__device__ __forceinline__ void red4(float* p, float a, float b, float c, float d) {
    asm volatile("red.global.add.v4.f32 [%0], {%1,%2,%3,%4};"
                 :: "l"(p), "f"(a), "f"(b), "f"(c), "f"(d) : "memory");
}

// ---------------- CSR hist + fused weight prep ----------------
__global__ void k_hist(const int* __restrict__ dst, const float* __restrict__ WL,
                       const float* __restrict__ W1) {
    int b = blockIdx.x;
    int e = b * 256 + threadIdx.x;
    if (e < NE) atomicAdd(&g_count[dst[e]], 1);
    if (b < LAYERS) {
        const float* Wn = WL + (size_t)b * 5 * 4096;
        for (int q = threadIdx.x; q < 4 * 4096; q += 256) {
            int j = q >> 12, k = (q >> 6) & 63, c = q & 63;
            float x = Wn[q];
            __nv_bfloat16 h = __float2bfloat16(x);
            g_WnT[b][0][j * 64 + c][k] = h;
            g_WnT[b][1][j * 64 + c][k] = __float2bfloat16(x - __bfloat162float(h));
        }
        const float* Wc = WL + (size_t)b * 5 * 4096 + 4 * 4096;
        for (int q = threadIdx.x; q < 4096; q += 256) {
            int k = q >> 6, c = q & 63;
            float x = Wc[q];
            __nv_bfloat16 h = __float2bfloat16(x);
            g_WcT[b][0][c][k] = h;
            g_WcT[b][1][c][k] = __float2bfloat16(x - __bfloat162float(h));
        }
    } else if (b == LAYERS) {
        for (int q = threadIdx.x; q < 8192; q += 256) {
            int k = q >> 7, c = q & 127;
            float x = W1[q];
            __nv_bfloat16 h = __float2bfloat16(x);
            g_W1T[0][c][k] = h;
            g_W1T[1][c][k] = __float2bfloat16(x - __bfloat162float(h));
        }
    }
}

__global__ void k_scan() {   // single block; self-zeroes g_count for replay
    __shared__ int part[1024];
    int tid = threadIdx.x;
    const int CH = (NN + 1023) / 1024;
    int base = tid * CH;
    int s = 0;
    for (int i = 0; i < CH; i++) { int idx = base + i; if (idx < NN) s += g_count[idx]; }
    part[tid] = s;
    __syncthreads();
    for (int off = 1; off < 1024; off <<= 1) {
        int v = (tid >= off) ? part[tid - off] : 0;
        __syncthreads();
        part[tid] += v;
        __syncthreads();
    }
    int excl = part[tid] - s;
    for (int i = 0; i < CH; i++) {
        int idx = base + i;
        if (idx < NN) {
            int c = g_count[idx];
            g_rowstart[idx] = excl;
            g_cursor[idx] = excl;
            excl += c;
            g_count[idx] = 0;
        }
    }
    if (tid == 1023) g_rowstart[NN] = part[1023];
}
__global__ void k_scatter(const int* __restrict__ src, const int* __restrict__ dst) {
    int e = blockIdx.x * blockDim.x + threadIdx.x;
    if (e < NE) {
        int d = dst[e];
        int pos = atomicAdd(&g_cursor[d], 1);
        g_perm_src[pos] = src[e];
        g_perm_dst[pos] = d;
        g_perm_eid[pos] = e;
    }
}

// ---------------- node MMA GEMM: C[M, nq*64] = A[M,64] @ W + bias ----------------
__global__ void __launch_bounds__(256, 5) k_node_mma(
    const __nv_bfloat16* __restrict__ WT,
    const float* __restrict__ bias, float* __restrict__ C,
    int M, int nq, int ldc, int relu,
    const float* __restrict__ hf, const float* __restrict__ Wemb,
    const float* __restrict__ bemb, int embedH, int updateH)
{
    __shared__ __align__(16) __nv_bfloat16 Apl[2][64 * AP];
    __shared__ __align__(16) __nv_bfloat16 Wq[2][64 * AP];
    int n0 = blockIdx.x * 64;
    int t = threadIdx.x;
    int lane = t & 31, w = t >> 5;
    int nTot = nq * 64;

#pragma unroll
    for (int i = 0; i < 4; i++) {
        int q = i * 256 + t;
        int row = q >> 4, c0 = (q & 15) * 4;
        int m = n0 + row;
        float4 v = make_float4(0.f, 0.f, 0.f, 0.f);
        if (m < M) {
            if (embedH) {
                float f[6];
#pragma unroll
                for (int j = 0; j < 6; j++) f[j] = hf[m * 6 + j];
                v = *(const float4*)(bemb + c0);
#pragma unroll
                for (int j = 0; j < 6; j++) {
                    float4 wv = *(const float4*)(Wemb + j * 64 + c0);
                    v.x = fmaf(f[j], wv.x, v.x);
                    v.y = fmaf(f[j], wv.y, v.y);
                    v.z = fmaf(f[j], wv.z, v.z);
                    v.w = fmaf(f[j], wv.w, v.w);
                }
                *(float4*)(g_h + (size_t)m * 64 + c0) = v;
            } else if (updateH) {
                float4 hv = *(const float4*)(g_h + (size_t)m * 64 + c0);
                float4 ah = *(const float4*)(g_nodeT + (size_t)m * 256 + c0);
                float4 nu = *(const float4*)(g_num + (size_t)m * 64 + c0);
                float4 de = *(const float4*)(g_den + (size_t)m * 64 + c0);
                *(float4*)(g_num + (size_t)m * 64 + c0) = make_float4(0.f, 0.f, 0.f, 0.f);
                *(float4*)(g_den + (size_t)m * 64 + c0) = make_float4(0.f, 0.f, 0.f, 0.f);
                v.x = hv.x + fmaxf(ah.x + nu.x * __fdividef(1.f, de.x + 1e-6f), 0.f);
                v.y = hv.y + fmaxf(ah.y + nu.y * __fdividef(1.f, de.y + 1e-6f), 0.f);
                v.z = hv.z + fmaxf(ah.z + nu.z * __fdividef(1.f, de.z + 1e-6f), 0.f);
                v.w = hv.w + fmaxf(ah.w + nu.w * __fdividef(1.f, de.w + 1e-6f), 0.f);
                *(float4*)(g_h + (size_t)m * 64 + c0) = v;
            } else {
                v = *(const float4*)(g_h + (size_t)m * 64 + c0);
            }
        }
        u32 p0 = packsplit(v.x), p1 = packsplit(v.y);
        u32 p2 = packsplit(v.z), p3 = packsplit(v.w);
        *(uint2*)&Apl[0][row * AP + c0] =
            make_uint2(__byte_perm(p0, p1, 0x5410), __byte_perm(p2, p3, 0x5410));
        *(uint2*)&Apl[1][row * AP + c0] =
            make_uint2(__byte_perm(p0, p1, 0x7632), __byte_perm(p2, p3, 0x7632));
    }

    int ms = w >> 1, nh = w & 1;
    int gid = lane >> 2, tig = lane & 3;

    u32 aOff = (u32)(((ms * 16 + (lane & 7) + ((lane >> 3) & 1) * 8) * AP +
                      (lane >> 4) * 8) * 2);
    u32 aHiB = s2u(&Apl[0][0]) + aOff;
    u32 aLoB = s2u(&Apl[1][0]) + aOff;
    u32 bB[4];
#pragma unroll
    for (int nt = 0; nt < 4; nt++) {
        int nrow = nh * 32 + nt * 8 + (lane & 7);
        bB[nt] = s2u(&Wq[0][0]) +
                 (u32)((nrow * AP + ((lane >> 3) & 1) * 8) * 2) +
                 (u32)((lane >> 4) * 64 * AP * 2);
    }

    for (int q = 0; q < nq; q++) {
        __syncthreads();
        {
            int n = t >> 2, ks = (t & 3) * 16;
            const __nv_bfloat16* Wh = WT + (size_t)(q * 64 + n) * 64;
            const __nv_bfloat16* Wl = WT + (size_t)nTot * 64 + (size_t)(q * 64 + n) * 64;
            *(uint4*)&Wq[0][n * AP + ks]     = *(const uint4*)(Wh + ks);
            *(uint4*)&Wq[0][n * AP + ks + 8] = *(const uint4*)(Wh + ks + 8);
            *(uint4*)&Wq[1][n * AP + ks]     = *(const uint4*)(Wl + ks);
            *(uint4*)&Wq[1][n * AP + ks + 8] = *(const uint4*)(Wl + ks + 8);
        }
        __syncthreads();

        float c[4][4];
#pragma unroll
        for (int nt = 0; nt < 4; nt++)
#pragma unroll
            for (int j = 0; j < 4; j++) c[nt][j] = 0.f;

#pragma unroll
        for (int kc = 0; kc < 4; kc++) {
            u32 ko = kc * 32;
            u32 a0h, a1h, a2h, a3h, a0l, a1l, a2l, a3l;
            ldsm4(a0h, a1h, a2h, a3h, aHiB + ko);
            ldsm4(a0l, a1l, a2l, a3l, aLoB + ko);
#pragma unroll
            for (int nt = 0; nt < 4; nt++) {
                u32 b0h, b1h, b0l, b1l;
                ldsm4(b0h, b1h, b0l, b1l, bB[nt] + ko);
                mma16816(c[nt], a0h, a1h, a2h, a3h, b0h, b1h);
                mma16816(c[nt], a0h, a1h, a2h, a3h, b0l, b1l);
                mma16816(c[nt], a0l, a1l, a2l, a3l, b0h, b1h);
            }
        }

#pragma unroll
        for (int nt = 0; nt < 4; nt++) {
            int col = q * 64 + nh * 32 + nt * 8 + tig * 2;
            int r = n0 + ms * 16 + gid;
            float b0 = bias[col], b1 = bias[col + 1];
            float2 v0 = make_float2(c[nt][0] + b0, c[nt][1] + b1);
            float2 v1 = make_float2(c[nt][2] + b0, c[nt][3] + b1);
            if (relu) {
                v0.x = fmaxf(v0.x, 0.f); v0.y = fmaxf(v0.y, 0.f);
                v1.x = fmaxf(v1.x, 0.f); v1.y = fmaxf(v1.y, 0.f);
            }
            if (r < M)     *(float2*)(C + (size_t)r * ldc + col)       = v0;
            if (r + 8 < M) *(float2*)(C + (size_t)(r + 8) * ldc + col) = v1;
        }
    }
}

// ---------------- fused edge MMA + gate + e-residual + direct red.v4 reduction ----------------
#define OFF_ALO   9216
#define OFF_WT    18432
#define OFF_WTLO  27648
#define OFF_SRC   36864
#define OFF_DST   37120
#define OFF_EF    37376
// Cs (float[64][68]=17408B) overlays W planes [18432, 36864): Ce stage

__global__ void __launch_bounds__(256, 5) k_edge_gemm(
    const __nv_bfloat16* __restrict__ WT, const float* __restrict__ bc,
    const float* __restrict__ We, const float* __restrict__ be,
    const float* __restrict__ ef, int embed, int last)
{
    __shared__ __align__(16) char sm[37888];
    __nv_bfloat16* Ahi = (__nv_bfloat16*)sm;
    __nv_bfloat16* Alo = (__nv_bfloat16*)(sm + OFF_ALO);
    __nv_bfloat16* Wth = (__nv_bfloat16*)(sm + OFF_WT);
    __nv_bfloat16* Wtl = (__nv_bfloat16*)(sm + OFF_WTLO);
    float* Cs = (float*)(sm + OFF_WT);   // Ce stage (over dead W planes)
    int*   sSrc = (int*)(sm + OFF_SRC);
    int*   sDst = (int*)(sm + OFF_DST);
    float2* sEf = (float2*)(sm + OFF_EF);

    int p0 = blockIdx.x * 64;
    int t = threadIdx.x;
    int lane = t & 31, w = t >> 5;
    int tx = t & 15, ty = t >> 4;

    if (t < 64) {
        sSrc[t] = g_perm_src[p0 + t];
        sDst[t] = g_perm_dst[p0 + t];
        if (embed) sEf[t] = ((const float2*)ef)[g_perm_eid[p0 + t]];
    }
    {
        int n = t >> 2, ks = (t & 3) * 16;
        *(uint4*)&Wth[n * AP + ks]     = *(const uint4*)(WT + n * 64 + ks);
        *(uint4*)&Wth[n * AP + ks + 8] = *(const uint4*)(WT + n * 64 + ks + 8);
        *(uint4*)&Wtl[n * AP + ks]     = *(const uint4*)(WT + 4096 + n * 64 + ks);
        *(uint4*)&Wtl[n * AP + ks + 8] = *(const uint4*)(WT + 4096 + n * 64 + ks + 8);
    }
    __syncthreads();   // B0: sEf ready for embed A-build

#pragma unroll
    for (int i = 0; i < 4; i++) {
        int q = i * 256 + t;
        int row = q >> 4, c0 = (q & 15) * 4;
        uint4 u;
        if (embed) {
            float2 efv = sEf[row];
            float4 w0 = *(const float4*)(We + c0);
            float4 w1 = *(const float4*)(We + 64 + c0);
            float4 bb = *(const float4*)(be + c0);
            u.x = packsplit(fmaf(efv.x, w0.x, fmaf(efv.y, w1.x, bb.x)));
            u.y = packsplit(fmaf(efv.x, w0.y, fmaf(efv.y, w1.y, bb.y)));
            u.z = packsplit(fmaf(efv.x, w0.z, fmaf(efv.y, w1.z, bb.z)));
            u.w = packsplit(fmaf(efv.x, w0.w, fmaf(efv.y, w1.w, bb.w)));
        } else {
            u = *(const uint4*)&g_e[(size_t)(p0 + row) * 64 + c0];
        }
        *(uint2*)&Ahi[row * AP + c0] =
            make_uint2(__byte_perm(u.x, u.y, 0x5410), __byte_perm(u.z, u.w, 0x5410));
        *(uint2*)&Alo[row * AP + c0] =
            make_uint2(__byte_perm(u.x, u.y, 0x7632), __byte_perm(u.z, u.w, 0x7632));
    }
    __syncthreads();   // B1: A planes ready

    int ms = w >> 1, nh = w & 1;
    int gid = lane >> 2, tig = lane & 3;

    u32 aOff = (u32)(((ms * 16 + (lane & 7) + ((lane >> 3) & 1) * 8) * AP +
                      (lane >> 4) * 8) * 2);
    u32 aHiB = s2u(Ahi) + aOff;
    u32 aLoB = s2u(Alo) + aOff;
    u32 bB[4];
#pragma unroll
    for (int nt = 0; nt < 4; nt++) {
        int nrow = nh * 32 + nt * 8 + (lane & 7);
        bB[nt] = s2u(Wth) +
                 (u32)((nrow * AP + ((lane >> 3) & 1) * 8) * 2) +
                 (u32)((lane >> 4) * (OFF_WTLO - OFF_WT));
    }

    float c[4][4];
#pragma unroll
    for (int nt = 0; nt < 4; nt++)
#pragma unroll
        for (int j = 0; j < 4; j++) c[nt][j] = 0.f;

#pragma unroll
    for (int kc = 0; kc < 4; kc++) {
        u32 ko = kc * 32;
        u32 a0h, a1h, a2h, a3h, a0l, a1l, a2l, a3l;
        ldsm4(a0h, a1h, a2h, a3h, aHiB + ko);
        ldsm4(a0l, a1l, a2l, a3l, aLoB + ko);
#pragma unroll
        for (int nt = 0; nt < 4; nt++) {
            u32 b0h, b1h, b0l, b1l;
            ldsm4(b0h, b1h, b0l, b1l, bB[nt] + ko);
            mma16816(c[nt], a0h, a1h, a2h, a3h, b0h, b1h);
            mma16816(c[nt], a0h, a1h, a2h, a3h, b0l, b1l);
            mma16816(c[nt], a0l, a1l, a2l, a3l, b0h, b1h);
        }
    }
    __syncthreads();   // B2: all ldsm done -> Cs overlay of W planes safe

    // stage Ce fragments
#pragma unroll
    for (int nt = 0; nt < 4; nt++) {
        int col = nh * 32 + nt * 8 + tig * 2;
        int r = ms * 16 + gid;
        *(float2*)&Cs[r * 68 + col]       = make_float2(c[nt][0], c[nt][1]);
        *(float2*)&Cs[(r + 8) * 68 + col] = make_float2(c[nt][2], c[nt][3]);
    }
    __syncthreads();   // B3: Ce staged

    float bb0 = bc[tx * 4 + 0], bb1 = bc[tx * 4 + 1];
    float bb2 = bc[tx * 4 + 2], bb3 = bc[tx * 4 + 3];

    // Gate + e-residual + run-aggregated direct reduction (red.v4 flushes).
    // Thread owns rows ty*4..ty*4+3 x cols tx*4..tx*4+3 (dst-sorted rows).
    {
        float an0 = 0.f, an1 = 0.f, an2 = 0.f, an3 = 0.f;
        float ad0 = 0.f, ad1 = 0.f, ad2 = 0.f, ad3 = 0.f;
        int curd = sDst[ty * 4];
#pragma unroll
        for (int r = 0; r < 4; r++) {
            int row = ty * 4 + r;
            int p = p0 + row;
            int dn = sDst[row], sn = sSrc[row];
            if (dn != curd) {   // flush finished run
                red4(g_num + (size_t)curd * 64 + tx * 4, an0, an1, an2, an3);
                red4(g_den + (size_t)curd * 64 + tx * 4, ad0, ad1, ad2, ad3);
                an0 = an1 = an2 = an3 = 0.f;
                ad0 = ad1 = ad2 = ad3 = 0.f;
                curd = dn;
            }
            float4 dh = *(const float4*)(g_nodeT + (size_t)dn * 256 + 128 + tx * 4);
            float4 eh = *(const float4*)(g_nodeT + (size_t)sn * 256 + 192 + tx * 4);
            float4 bh = *(const float4*)(g_nodeT + (size_t)sn * 256 +  64 + tx * 4);
            float4 ce = *(const float4*)&Cs[row * 68 + tx * 4];
            uint2 hu = *(const uint2*)&Ahi[row * AP + tx * 4];
            uint2 lu = *(const uint2*)&Alo[row * AP + tx * 4];
            float eo0 = frombits(hu.x & 0xffffu, lu.x & 0xffffu);
            float eo1 = frombits(hu.x >> 16,     lu.x >> 16);
            float eo2 = frombits(hu.y & 0xffffu, lu.y & 0xffffu);
            float eo3 = frombits(hu.y >> 16,     lu.y >> 16);
            float t0 = ce.x + bb0 + dh.x + eh.x;
            float t1 = ce.y + bb1 + dh.y + eh.y;
            float t2 = ce.z + bb2 + dh.z + eh.z;
            float t3 = ce.w + bb3 + dh.w + eh.w;
            float s0 = fsig(t0), s1 = fsig(t1), s2 = fsig(t2), s3 = fsig(t3);
            if (!last) {
                uint4 en;
                en.x = packsplit(eo0 + fmaxf(t0, 0.f));
                en.y = packsplit(eo1 + fmaxf(t1, 0.f));
                en.z = packsplit(eo2 + fmaxf(t2, 0.f));
                en.w = packsplit(eo3 + fmaxf(t3, 0.f));
                *(uint4*)&g_e[(size_t)p * 64 + tx * 4] = en;
            }
            an0 = fmaf(s0, bh.x, an0); an1 = fmaf(s1, bh.y, an1);
            an2 = fmaf(s2, bh.z, an2); an3 = fmaf(s3, bh.w, an3);
            ad0 += s0; ad1 += s1; ad2 += s2; ad3 += s3;
        }
        // final flush
        red4(g_num + (size_t)curd * 64 + tx * 4, an0, an1, an2, an3);
        red4(g_den + (size_t)curd * 64 + tx * 4, ad0, ad1, ad2, ad3);
    }
}

// ---------------- MLP head tail ----------------
__global__ void k_head(const float* __restrict__ W2, const float* __restrict__ b2,
                       float* __restrict__ out) {
    int gtid = blockIdx.x * blockDim.x + threadIdx.x;
    int n = gtid >> 5;
    if (n >= NN) return;
    int lane = gtid & 31;
    float s0 = 0.f, s1 = 0.f;
#pragma unroll
    for (int t = 0; t < 4; t++) {
        int k = lane + t * 32;
        float v = g_mlp[n * 128 + k];
        s0 = fmaf(v, W2[k * 2 + 0], s0);
        s1 = fmaf(v, W2[k * 2 + 1], s1);
    }
#pragma unroll
    for (int off = 16; off; off >>= 1) {
        s0 += __shfl_xor_sync(0xffffffffu, s0, off);
        s1 += __shfl_xor_sync(0xffffffffu, s1, off);
    }
    if (lane == 0) {
        out[n * 2 + 0] = -1.2f * tanhf(s0 + b2[0]);
        out[n * 2 + 1] = -1.2f * tanhf(s1 + b2[1]);
    }
}

// ---------------- launch ----------------
extern "C" void kernel_launch(void* const* d_in, const int* in_sizes, int n_in,
                              void* d_out, int out_size) {
    const float* h_feat  = (const float*)d_in[0];
    const float* e_feat  = (const float*)d_in[1];
    const int*   src     = (const int*)d_in[2];
    const int*   dst     = (const int*)d_in[3];
    const float* W_emb_h = (const float*)d_in[4];
    const float* b_emb_h = (const float*)d_in[5];
    const float* W_emb_e = (const float*)d_in[6];
    const float* b_emb_e = (const float*)d_in[7];
    const float* WL      = (const float*)d_in[8];
    const float* bL      = (const float*)d_in[9];
    const float* W1      = (const float*)d_in[10];
    const float* b1      = (const float*)d_in[11];
    const float* W2      = (const float*)d_in[12];
    const float* b2      = (const float*)d_in[13];
    float* out = (float*)d_out;

    void *p_nodeT, *p_mlp, *p_WnT, *p_WcT, *p_W1T;
    cudaGetSymbolAddress(&p_nodeT, g_nodeT);
    cudaGetSymbolAddress(&p_mlp, g_mlp);
    cudaGetSymbolAddress(&p_WnT, g_WnT);
    cudaGetSymbolAddress(&p_WcT, g_WcT);
    cudaGetSymbolAddress(&p_W1T, g_W1T);

    // CSR build (hist fuses weight split/transpose prep)
    k_hist<<<(NE + 255) / 256, 256>>>(dst, WL, W1);
    k_scan<<<1, 1024>>>();
    k_scatter<<<(NE + 255) / 256, 256>>>(src, dst);

    for (int l = 0; l < LAYERS; l++) {
        const float* bl = bL + (size_t)l * 5 * HID;
        const __nv_bfloat16* WnT =
            (const __nv_bfloat16*)p_WnT + (size_t)l * 2 * 256 * 64;
        const __nv_bfloat16* WcT =
            (const __nv_bfloat16*)p_WcT + (size_t)l * 2 * 64 * 64;
        k_node_mma<<<(NN + 63) / 64, 256>>>(
            WnT, bl, (float*)p_nodeT, NN, 4, 256, 0,
            h_feat, W_emb_h, b_emb_h, l == 0, l > 0);
        k_edge_gemm<<<NE / 64, 256>>>(WcT, bl + 4 * 64,
                                      W_emb_e, b_emb_e, e_feat,
                                      l == 0, l == LAYERS - 1);
    }

    k_node_mma<<<(NN + 63) / 64, 256>>>(
        (const __nv_bfloat16*)p_W1T, b1, (float*)p_mlp, NN, 2, 128, 1,
        (const float*)0, (const float*)0, (const float*)0, 0, 1);
    k_head<<<(NN * 32 + 255) / 256, 256>>>(W2, b2, out);
}